// round 1
// baseline (speedup 1.0000x reference)
#include <cuda_runtime.h>
#include <math.h>

// SSIM loss, fully fused single-pass:
//   5 separable 11-tap Gaussian blurs (vertical in registers, horizontal via smem row buffer)
//   + SSIM map + global mean reduction.
// Inputs: img1, img2  float32 [16,1,1024,1024]. Output: float32 scalar (1 - mean(ssim)).

#define IMG_H 1024
#define IMG_W 1024
#define W_OUT 118          // output columns per block
#define EW    128          // extended columns (with 2*5 halo) == blockDim.x
#define ROWS  128          // output rows per block

__device__ double g_acc;

__global__ void zero_acc_kernel() { g_acc = 0.0; }

__global__ void finalize_kernel(float* out) {
    out[0] = (float)(1.0 - g_acc / (double)(16ull * 1024ull * 1024ull));
}

__global__ __launch_bounds__(EW) void ssim_kernel(const float* __restrict__ img1,
                                                  const float* __restrict__ img2) {
    const int tid = threadIdx.x;
    const int bx  = blockIdx.x;   // 0..8  (column strips of 118)
    const int by  = blockIdx.y;   // 0..7  (row strips of 128)
    const int bz  = blockIdx.z;   // 0..15 (batch)
    const long long base = (long long)bz * (long long)(IMG_H * IMG_W);

    const int xg  = bx * W_OUT - 5 + tid;          // global column this thread loads
    const bool xok = (xg >= 0) && (xg < IMG_W);
    const int y0  = by * ROWS;

    // Gaussian weights, matching the numpy float32 computation:
    // exp in double -> cast f32 -> sum f32 -> divide f32
    float w[11];
    {
        float g[11];
        #pragma unroll
        for (int i = 0; i < 11; ++i) {
            double d = (double)(i - 5);
            g[i] = (float)exp(-(d * d) / 4.5);
        }
        float s = 0.f;
        #pragma unroll
        for (int i = 0; i < 11; ++i) s += g[i];
        #pragma unroll
        for (int i = 0; i < 11; ++i) w[i] = g[i] / s;
    }

    __shared__ float sbuf[2][5][EW];   // double-buffered row of 5 vertical sums
    __shared__ float red[4];

    // Register ring buffers: row (y0-5+i) lives in slot i at prime time;
    // in general row ri -> slot (ri - (y0-5)) mod 11.
    float a[11], b[11];
    #pragma unroll
    for (int i = 0; i < 10; ++i) {
        int ri = y0 - 5 + i;
        bool ok = xok && (ri >= 0);           // ri < IMG_H guaranteed here
        long long off = base + (long long)ri * IMG_W + xg;
        a[i] = ok ? __ldg(img1 + off) : 0.f;
        b[i] = ok ? __ldg(img2 + off) : 0.f;
    }
    a[10] = 0.f; b[10] = 0.f;

    const float c1 = 0.0001f;   // 0.01^2
    const float c2 = 0.0009f;   // 0.03^2
    float acc = 0.f;

    // Row loop, unrolled by 11 so ring-buffer indices are compile-time constants.
    #pragma unroll 1
    for (int rb = 0; rb < ROWS; rb += 11) {
        #pragma unroll
        for (int p = 0; p < 11; ++p) {
            const int r = rb + p;
            if (r < ROWS) {   // uniform across block -> syncthreads inside is legal
                // Load new bottom row y0+r+5 into slot (p+10)%11
                {
                    const int ri = y0 + r + 5;
                    const bool ok = xok && (ri < IMG_H);
                    const long long off = base + (long long)ri * IMG_W + xg;
                    a[(p + 10) % 11] = ok ? __ldg(img1 + off) : 0.f;
                    b[(p + 10) % 11] = ok ? __ldg(img2 + off) : 0.f;
                }

                // Vertical 11-tap for all 5 fields (products formed on the fly)
                float s1 = 0.f, s2 = 0.f, s3 = 0.f, s4 = 0.f, s5 = 0.f;
                #pragma unroll
                for (int d = 0; d < 11; ++d) {
                    const int sl = (p + d) % 11;          // compile-time
                    const float av = a[sl], bv = b[sl];
                    const float wv = w[d];
                    const float ta = wv * av;
                    const float tb = wv * bv;
                    s1 += ta;
                    s2 += tb;
                    s3 = fmaf(ta, av, s3);
                    s4 = fmaf(tb, bv, s4);
                    s5 = fmaf(ta, bv, s5);
                }

                const int bufi = r & 1;
                sbuf[bufi][0][tid] = s1;
                sbuf[bufi][1][tid] = s2;
                sbuf[bufi][2][tid] = s3;
                sbuf[bufi][3][tid] = s4;
                sbuf[bufi][4][tid] = s5;
                __syncthreads();

                // Horizontal 11-tap + SSIM (interior columns only)
                if (tid >= 5 && tid < 5 + W_OUT && xg < IMG_W) {
                    float h1 = 0.f, h2 = 0.f, h3 = 0.f, h4 = 0.f, h5 = 0.f;
                    #pragma unroll
                    for (int k = 0; k < 11; ++k) {
                        const float wv = w[k];
                        const int xx = tid - 5 + k;
                        h1 = fmaf(wv, sbuf[bufi][0][xx], h1);
                        h2 = fmaf(wv, sbuf[bufi][1][xx], h2);
                        h3 = fmaf(wv, sbuf[bufi][2][xx], h3);
                        h4 = fmaf(wv, sbuf[bufi][3][xx], h4);
                        h5 = fmaf(wv, sbuf[bufi][4][xx], h5);
                    }
                    const float mu1 = h1, mu2 = h2;
                    const float mu1s = mu1 * mu1;
                    const float mu2s = mu2 * mu2;
                    const float mu12 = mu1 * mu2;
                    const float sg1  = h3 - mu1s;
                    const float sg2  = h4 - mu2s;
                    const float sg12 = h5 - mu12;
                    const float num = (2.f * mu12 + c1) * (2.f * sg12 + c2);
                    const float den = (mu1s + mu2s + c1) * (sg1 + sg2 + c2);
                    acc += __fdividef(num, den);
                }
                // Double buffering + the sync above makes one barrier per row safe:
                // readers of buffer (r&1) are strictly before the next write to it.
            }
        }
    }

    // Block reduction -> one double atomic per CTA
    #pragma unroll
    for (int o = 16; o; o >>= 1) acc += __shfl_xor_sync(0xffffffffu, acc, o);
    if ((tid & 31) == 0) red[tid >> 5] = acc;
    __syncthreads();
    if (tid == 0) {
        float t = red[0] + red[1] + red[2] + red[3];
        atomicAdd(&g_acc, (double)t);
    }
}

extern "C" void kernel_launch(void* const* d_in, const int* in_sizes, int n_in,
                              void* d_out, int out_size) {
    const float* img1 = (const float*)d_in[0];
    const float* img2 = (const float*)d_in[1];
    float* out = (float*)d_out;

    zero_acc_kernel<<<1, 1>>>();

    dim3 grid((IMG_W + W_OUT - 1) / W_OUT, IMG_H / ROWS, 16);  // (9, 8, 16)
    ssim_kernel<<<grid, EW>>>(img1, img2);

    finalize_kernel<<<1, 1>>>(out);
}